// round 4
// baseline (speedup 1.0000x reference)
#include <cuda_runtime.h>
#include <cuda_bf16.h>

// AdaptiveEMA via block-parallel linear-recurrence scan.
//   e[t] = a*e[t-1] + x[t]  (infinite EMA, Kogge-Stone scan of affine maps)
//   num[t] = e[t] - a^K * e[t-K]   (exact telescope of the K=201-tap window)
//   out[t] = num[t] / (geometric weight sum)
// One CTA per (b,f) channel: 256 threads x 16 contiguous elements.
// vs R2: e[t] kept in registers (only e[t-201] read from smem),
// vectorized float4 output stores, no remap phase. Halves L1tex traffic.

#define S_LEN 4096
#define TPB 256
#define PER_THREAD 16
#define KWIN 201
#define NWARPS (TPB / 32)

// stride-17 padded smem index -> conflict-free for both stride-1-per-thread
// writes and stride-16-across-lanes accesses
__device__ __forceinline__ int pidx(int t) { return t + (t >> 4); }

__global__ __launch_bounds__(TPB) void adaptive_ema_kernel(
    const float* __restrict__ x,
    const float* __restrict__ log_hl,
    float* __restrict__ out,
    int F)
{
    __shared__ float e_s[S_LEN + (S_LEN / 16)];
    __shared__ float aggC[NWARPS], aggV[NWARPS];

    const int c    = blockIdx.x;
    const int f    = c % F;
    const int tid  = threadIdx.x;
    const int lane = tid & 31;
    const int wid  = tid >> 5;

    // ---- per-channel constants ----
    const float hl      = expf(log_hl[f]);
    const float inv_hl  = 1.0f / hl;
    const float a       = exp2f(-inv_hl);                          // alpha
    const float one_m_a = -expm1f(-0.69314718055994531f * inv_hl); // 1-alpha
    const float inv_1ma = 1.0f / one_m_a;
    const float aK      = exp2f(-(float)KWIN * inv_hl);            // alpha^201
    const float r_const = 1.0f / ((1.0f - aK) * inv_1ma + 1e-8f);

    const float* xc = x   + (size_t)c * S_LEN;
    float*       oc = out + (size_t)c * S_LEN;

    const int base = tid * PER_THREAD;

    // ---- load 16 contiguous elements (4x LDG.128, coalesced) ----
    float v[PER_THREAD];
    const float4* xb = reinterpret_cast<const float4*>(xc + base);
    #pragma unroll
    for (int q = 0; q < 4; q++) {
        float4 t4 = xb[q];
        v[4*q+0] = t4.x; v[4*q+1] = t4.y; v[4*q+2] = t4.z; v[4*q+3] = t4.w;
    }

    // ---- local serial scan ----
    float e = 0.0f;
    #pragma unroll
    for (int j = 0; j < PER_THREAD; j++) {
        e = fmaf(a, e, v[j]);
        v[j] = e;
    }

    // segment affine transform: E_out = C*E_in + V, C = a^16
    const float a2 = a * a, a4 = a2 * a2, a8 = a4 * a4;
    float C = a8 * a8;
    float V = e;

    // ---- Kogge-Stone warp scan over affine maps ----
    #pragma unroll
    for (int d = 1; d < 32; d <<= 1) {
        float Cp = __shfl_up_sync(0xffffffffu, C, d);
        float Vp = __shfl_up_sync(0xffffffffu, V, d);
        if (lane >= d) {
            V = fmaf(C, Vp, V);
            C = C * Cp;
        }
    }
    if (lane == 31) { aggC[wid] = C; aggV[wid] = V; }

    // lane-exclusive (shift by one; lane 0 identity)
    float Cx = __shfl_up_sync(0xffffffffu, C, 1);
    float Vx = __shfl_up_sync(0xffffffffu, V, 1);
    if (lane == 0) { Cx = 1.0f; Vx = 0.0f; }

    __syncthreads();

    // compose aggregates of preceding warps
    float Wv = 0.0f;
    #pragma unroll
    for (int w = 0; w < NWARPS; w++) {
        if (w < wid) Wv = fmaf(aggC[w], Wv, aggV[w]);
    }
    const float Ein = fmaf(Cx, Wv, Vx);   // e just before this segment

    // ---- apply carry: v[j] becomes final e[base+j]; stage to smem for the
    //      cross-thread e[t-201] reads ----
    {
        float p = a;
        #pragma unroll
        for (int j = 0; j < PER_THREAD; j++) {
            float ej = fmaf(p, Ein, v[j]);
            v[j] = ej;
            e_s[pidx(base + j)] = ej;
            p *= a;
        }
    }
    __syncthreads();

    // ---- output: e[t] from registers, e[t-201] from smem, float4 stores ----
    float4* ob = reinterpret_cast<float4*>(oc + base);
    #pragma unroll
    for (int q = 0; q < 4; q++) {
        float r4[4];
        #pragma unroll
        for (int u = 0; u < 4; u++) {
            const int j = 4*q + u;
            const int t = base + j;
            float num = v[j];
            if (t >= KWIN) num = fmaf(-aK, e_s[pidx(t - KWIN)], num);
            float r;
            if (t < KWIN - 1) {
                float tw = (1.0f - exp2f(-(float)(t + 1) * inv_hl)) * inv_1ma;
                r = __fdividef(1.0f, tw + 1e-8f);
            } else {
                r = r_const;
            }
            r4[u] = num * r;
        }
        ob[q] = make_float4(r4[0], r4[1], r4[2], r4[3]);
    }
}

extern "C" void kernel_launch(void* const* d_in, const int* in_sizes, int n_in,
                              void* d_out, int out_size)
{
    const float* x      = (const float*)d_in[0];
    const float* log_hl = (const float*)d_in[1];
    float*       out    = (float*)d_out;

    const int F        = in_sizes[1];            // 256
    const int channels = in_sizes[0] / S_LEN;    // B*F

    adaptive_ema_kernel<<<channels, TPB>>>(x, log_hl, out, F);
}